// round 2
// baseline (speedup 1.0000x reference)
#include <cuda_runtime.h>
#include <math.h>

// 9 trig coefficients, computed on-device from params/W/b by setup_kernel.
// Order: [const, C0, C1, C0C1, S0, S1, S0C1, C0S1, S0S1]
__device__ float g_k[9];

struct cfl { float re, im; };

__device__ __forceinline__ cfl cmulf(cfl a, cfl b) {
    return { a.re * b.re - a.im * b.im, a.re * b.im + a.im * b.re };
}
__device__ __forceinline__ cfl caddf(cfl a, cfl b) { return { a.re + b.re, a.im + b.im }; }
__device__ __forceinline__ cfl cexpj(float t) { return { cosf(t), sinf(t) }; }
__device__ __forceinline__ cfl cconj(cfl a) { return { a.re, -a.im }; }

// C = A @ B  (4x4 complex, no aliasing with inputs required: uses temp)
__device__ void mm4(cfl C[4][4], const cfl A[4][4], const cfl B[4][4]) {
    cfl T[4][4];
    for (int i = 0; i < 4; i++)
        for (int j = 0; j < 4; j++) {
            cfl acc = { 0.f, 0.f };
            for (int k = 0; k < 4; k++) acc = caddf(acc, cmulf(A[i][k], B[k][j]));
            T[i][j] = acc;
        }
    for (int i = 0; i < 4; i++)
        for (int j = 0; j < 4; j++) C[i][j] = T[i][j];
}

__global__ void setup_kernel(const float* __restrict__ params,
                             const float* __restrict__ W,
                             const float* __restrict__ bias,
                             int L) {
    if (threadIdx.x != 0 || blockIdx.x != 0) return;

    // U = I
    cfl U[4][4];
    for (int i = 0; i < 4; i++)
        for (int j = 0; j < 4; j++) U[i][j] = { (i == j) ? 1.f : 0.f, 0.f };

    // CNOT (wire0 = control): rows [[1,0,0,0],[0,1,0,0],[0,0,0,1],[0,0,1,0]]
    cfl CN[4][4];
    for (int i = 0; i < 4; i++)
        for (int j = 0; j < 4; j++) CN[i][j] = { 0.f, 0.f };
    CN[0][0] = {1.f, 0.f}; CN[1][1] = {1.f, 0.f}; CN[2][3] = {1.f, 0.f}; CN[3][2] = {1.f, 0.f};

    // HH = kron(H, H)
    cfl HH[4][4];
    for (int i = 0; i < 4; i++)
        for (int j = 0; j < 4; j++) {
            float v = 0.5f;
            if ((i >> 1) & (j >> 1)) v = -v;
            if ((i & 1) & (j & 1)) v = -v;
            HH[i][j] = { v, 0.f };
        }

    for (int l = 0; l < L; l++) {
        float p[14];
        for (int j = 0; j < 14; j++) {
            float v = params[l * 14 + j];
            float lim = (j < 12) ? 5.f : 1.f;
            p[j] = fminf(fmaxf(v, -lim), lim);
        }

        // P = kron(phase(p2), phase(p3)) : diag(1, e^{ip3}, e^{ip2}, e^{i(p2+p3)})
        cfl Pm[4][4];
        for (int i = 0; i < 4; i++) for (int j = 0; j < 4; j++) Pm[i][j] = {0.f, 0.f};
        Pm[0][0] = {1.f, 0.f};
        Pm[1][1] = cexpj(p[3]);
        Pm[2][2] = cexpj(p[2]);
        Pm[3][3] = cexpj(p[2] + p[3]);

        // S = kron(rz(p4+p6), rz(p5+p7)); rz(t) = diag(e^{-it/2}, e^{it/2})
        cfl Sm[4][4];
        for (int i = 0; i < 4; i++) for (int j = 0; j < 4; j++) Sm[i][j] = {0.f, 0.f};
        float ta = p[4] + p[6], tb = p[5] + p[7];
        for (int i = 0; i < 4; i++) {
            float s0 = ((i >> 1) & 1) ? 0.5f : -0.5f;
            float s1 = (i & 1) ? 0.5f : -0.5f;
            Sm[i][i] = cexpj(s0 * ta + s1 * tb);
        }

        // D = kron(ry(p10)@rz(p8), ry(p11)@rz(p9))
        cfl m0[2][2], m1[2][2];
        {
            float c = cosf(0.5f * p[10]), s = sinf(0.5f * p[10]);
            cfl e0 = cexpj(-0.5f * p[8]), e1 = cexpj(0.5f * p[8]);
            m0[0][0] = cmulf({c, 0.f}, e0);  m0[0][1] = cmulf({-s, 0.f}, e1);
            m0[1][0] = cmulf({s, 0.f}, e0);  m0[1][1] = cmulf({c, 0.f}, e1);
        }
        {
            float c = cosf(0.5f * p[11]), s = sinf(0.5f * p[11]);
            cfl e0 = cexpj(-0.5f * p[9]), e1 = cexpj(0.5f * p[9]);
            m1[0][0] = cmulf({c, 0.f}, e0);  m1[0][1] = cmulf({-s, 0.f}, e1);
            m1[1][0] = cmulf({s, 0.f}, e0);  m1[1][1] = cmulf({c, 0.f}, e1);
        }
        cfl Dm[4][4];
        for (int i = 0; i < 4; i++)
            for (int j = 0; j < 4; j++)
                Dm[i][j] = cmulf(m0[i >> 1][j >> 1], m1[i & 1][j & 1]);

        // CP = diag(1,1,1, e^{i(p12+p13)})
        cfl CPm[4][4];
        for (int i = 0; i < 4; i++) for (int j = 0; j < 4; j++) CPm[i][j] = {0.f, 0.f};
        CPm[0][0] = {1.f, 0.f}; CPm[1][1] = {1.f, 0.f}; CPm[2][2] = {1.f, 0.f};
        CPm[3][3] = cexpj(p[12] + p[13]);

        // layer = CP @ D @ S @ P @ HH @ CNOT
        cfl T[4][4];
        mm4(T, HH, CN);
        mm4(T, Pm, T);
        mm4(T, Sm, T);
        mm4(T, Dm, T);
        mm4(T, CPm, T);
        // U = layer @ U
        mm4(U, T, U);
    }

    // M = U^H Z U, Z = diag(1,1,-1,-1);  M[j][k] = sum_i conj(U[i][j]) z_i U[i][k]
    cfl M[4][4];
    const float z[4] = { 1.f, 1.f, -1.f, -1.f };
    for (int j = 0; j < 4; j++)
        for (int k = 0; k < 4; k++) {
            cfl acc = { 0.f, 0.f };
            for (int i = 0; i < 4; i++) {
                cfl t = cmulf(cconj(U[i][j]), U[i][k]);
                acc.re += z[i] * t.re;
                acc.im += z[i] * t.im;
            }
            M[j][k] = acc;
        }

    // phases of the state amplitudes: s = (r0, -i r1, -i r2, -r3)
    const cfl ph[4] = { {1.f, 0.f}, {0.f, -1.f}, {0.f, -1.f}, {-1.f, 0.f} };
    float A[4][4];
    for (int j = 0; j < 4; j++)
        for (int k = 0; k < 4; k++) {
            cfl t = cmulf(cmulf(cconj(ph[j]), ph[k]), M[j][k]);
            A[j][k] = t.re;
        }

    // Half-angle collapse -> 9 trig coefficients (times 1/4)
    float cC  = A[0][0] + A[1][1] + A[2][2] + A[3][3];
    float cC0 = A[0][0] + A[1][1] - A[2][2] - A[3][3];
    float cC1 = A[0][0] - A[1][1] + A[2][2] - A[3][3];
    float cCC = A[0][0] - A[1][1] - A[2][2] + A[3][3];
    float cS1 = 2.f * (A[0][1] + A[2][3]);
    float cC0S1 = 2.f * (A[0][1] - A[2][3]);
    float cS0 = 2.f * (A[0][2] + A[1][3]);
    float cS0C1 = 2.f * (A[0][2] - A[1][3]);
    float cS0S1 = 2.f * (A[0][3] + A[1][2]);

    float w = 0.25f * W[0];
    g_k[0] = w * cC + bias[0];
    g_k[1] = w * cC0;
    g_k[2] = w * cC1;
    g_k[3] = w * cCC;
    g_k[4] = w * cS0;
    g_k[5] = w * cS1;
    g_k[6] = w * cS0C1;
    g_k[7] = w * cC0S1;
    g_k[8] = w * cS0S1;
}

__device__ __forceinline__ float eval_sample(float x0, float x1,
                                             float k0, float k1, float k2, float k3,
                                             float k4, float k5, float k6, float k7, float k8) {
    float s0, c0, s1, c1;
    __sincosf(x0, &s0, &c0);
    __sincosf(x1, &s1, &c1);
    float v = k0;
    v = fmaf(k1, c0, v);
    v = fmaf(k2, c1, v);
    v = fmaf(k3, c0 * c1, v);
    v = fmaf(k4, s0, v);
    v = fmaf(k5, s1, v);
    v = fmaf(k6, s0 * c1, v);
    v = fmaf(k7, c0 * s1, v);
    v = fmaf(k8, s0 * s1, v);
    return v;
}

// 4 samples / thread: two float4 loads of x (interleaved x0,x1), one float4 store.
__global__ void __launch_bounds__(256)
fraud_kernel(const float4* __restrict__ x, float4* __restrict__ out, int nq) {
    int t = blockIdx.x * blockDim.x + threadIdx.x;
    float k0 = g_k[0], k1 = g_k[1], k2 = g_k[2], k3 = g_k[3], k4 = g_k[4];
    float k5 = g_k[5], k6 = g_k[6], k7 = g_k[7], k8 = g_k[8];
    if (t < nq) {
        float4 a = x[2 * t];
        float4 b = x[2 * t + 1];
        float4 r;
        r.x = eval_sample(a.x, a.y, k0, k1, k2, k3, k4, k5, k6, k7, k8);
        r.y = eval_sample(a.z, a.w, k0, k1, k2, k3, k4, k5, k6, k7, k8);
        r.z = eval_sample(b.x, b.y, k0, k1, k2, k3, k4, k5, k6, k7, k8);
        r.w = eval_sample(b.z, b.w, k0, k1, k2, k3, k4, k5, k6, k7, k8);
        out[t] = r;
    }
}

// Scalar fallback for B not divisible by 4 (not hit for this problem's shapes).
__global__ void __launch_bounds__(256)
fraud_kernel_scalar(const float2* __restrict__ x, float* __restrict__ out, int B) {
    int t = blockIdx.x * blockDim.x + threadIdx.x;
    float k0 = g_k[0], k1 = g_k[1], k2 = g_k[2], k3 = g_k[3], k4 = g_k[4];
    float k5 = g_k[5], k6 = g_k[6], k7 = g_k[7], k8 = g_k[8];
    if (t < B) {
        float2 a = x[t];
        out[t] = eval_sample(a.x, a.y, k0, k1, k2, k3, k4, k5, k6, k7, k8);
    }
}

extern "C" void kernel_launch(void* const* d_in, const int* in_sizes, int n_in,
                              void* d_out, int out_size) {
    const float* x      = (const float*)d_in[0];
    const float* params = (const float*)d_in[1];
    const float* W      = (const float*)d_in[2];
    const float* bias   = (const float*)d_in[3];
    float* out = (float*)d_out;

    int L = in_sizes[1] / 14;
    setup_kernel<<<1, 1>>>(params, W, bias, L);

    int B = out_size;  // n_classes = 1 -> out_size == batch
    if ((B & 3) == 0) {
        int nq = B >> 2;
        int blocks = (nq + 255) / 256;
        fraud_kernel<<<blocks, 256>>>((const float4*)x, (float4*)out, nq);
    } else {
        int blocks = (B + 255) / 256;
        fraud_kernel_scalar<<<blocks, 256>>>((const float2*)x, out, B);
    }
}

// round 3
// speedup vs baseline: 1.5029x; 1.5029x over previous
#include <cuda_runtime.h>
#include <math.h>

// 9 trig coefficients, computed on-device from params/W/b by setup_kernel.
// Order: [const, C0, C1, C0C1, S0, S1, S0C1, C0S1, S0S1]
__device__ float g_k[9];

// ---------------------------------------------------------------------------
// Setup: one warp. Lane j (j = lane & 3) evolves column j of the total
// unitary U through the L layers. Each layer is
//     layer = CP @ D @ S @ P @ HH @ CNOT
// where S, P, CP are diagonal and D = kron(2x2, 2x2), HH@CNOT = G is a
// constant real +-0.5 matrix. So per-layer update on a column vector u:
//     u <- CPdiag * ( D @ ( diag(S*P) * (G @ u) ) )
// After L layers, fold the state phases ph = (1,-i,-i,-1) into the columns
// (V = U diag(ph)); then the observable coefficients are pure REAL dot
// products of V's columns against z = (1,1,-1,-1).
// ---------------------------------------------------------------------------
__global__ void setup_kernel(const float* __restrict__ params,
                             const float* __restrict__ W,
                             const float* __restrict__ bias,
                             int L) {
    const unsigned FULL = 0xFFFFFFFFu;
    int lane = threadIdx.x;
    int col = lane & 3;

    // u = e_col
    float ur[4], ui[4];
    #pragma unroll
    for (int i = 0; i < 4; i++) { ur[i] = (i == col) ? 1.f : 0.f; ui[i] = 0.f; }

    for (int l = 0; l < L; l++) {
        float p[14];
        #pragma unroll
        for (int j = 0; j < 14; j++) {
            float v = params[l * 14 + j];
            float lim = (j < 12) ? 5.f : 1.f;
            p[j] = fminf(fmaxf(v, -lim), lim);
        }

        // ---- t = G @ u, G[i][j] = HH[i][k(j)], k: 0,1,3,2 ; entries +-0.5
        float tr[4], ti[4];
        #pragma unroll
        for (int i = 0; i < 4; i++) {
            float ar = 0.f, ai = 0.f;
            #pragma unroll
            for (int j = 0; j < 4; j++) {
                int jp = (j < 2) ? j : (5 - j);   // CNOT column map: 2<->3
                float s = 0.5f;
                if ((i >> 1) & (jp >> 1)) s = -s;
                if ((i & 1) & (jp & 1))   s = -s;
                ar = fmaf(s, ur[j], ar);
                ai = fmaf(s, ui[j], ai);
            }
            tr[i] = ar; ti[i] = ai;
        }

        // ---- diag(S*P): theta_i = p2*(i>>1) + p3*(i&1) + (+-ta/2) + (+-tb/2)
        float ta = p[4] + p[6], tb = p[5] + p[7];
        #pragma unroll
        for (int i = 0; i < 4; i++) {
            float th = p[2] * (float)((i >> 1) & 1) + p[3] * (float)(i & 1)
                     + (((i >> 1) & 1) ? 0.5f : -0.5f) * ta
                     + ((i & 1) ? 0.5f : -0.5f) * tb;
            float sn, cs; __sincosf(th, &sn, &cs);
            float r = tr[i] * cs - ti[i] * sn;
            float im = tr[i] * sn + ti[i] * cs;
            tr[i] = r; ti[i] = im;
        }

        // ---- D = kron(ry(p10)@rz(p8), ry(p11)@rz(p9)); apply as 4x4 mv
        float m0r[2][2], m0i[2][2], m1r[2][2], m1i[2][2];
        {
            float c, s, e0s, e0c, e1s, e1c;
            __sincosf(0.5f * p[10], &s, &c);
            __sincosf(-0.5f * p[8], &e0s, &e0c);
            __sincosf( 0.5f * p[8], &e1s, &e1c);
            m0r[0][0] =  c * e0c; m0i[0][0] =  c * e0s;
            m0r[0][1] = -s * e1c; m0i[0][1] = -s * e1s;
            m0r[1][0] =  s * e0c; m0i[1][0] =  s * e0s;
            m0r[1][1] =  c * e1c; m0i[1][1] =  c * e1s;
        }
        {
            float c, s, e0s, e0c, e1s, e1c;
            __sincosf(0.5f * p[11], &s, &c);
            __sincosf(-0.5f * p[9], &e0s, &e0c);
            __sincosf( 0.5f * p[9], &e1s, &e1c);
            m1r[0][0] =  c * e0c; m1i[0][0] =  c * e0s;
            m1r[0][1] = -s * e1c; m1i[0][1] = -s * e1s;
            m1r[1][0] =  s * e0c; m1i[1][0] =  s * e0s;
            m1r[1][1] =  c * e1c; m1i[1][1] =  c * e1s;
        }
        float nr[4], ni[4];
        #pragma unroll
        for (int i = 0; i < 4; i++) {
            float ar = 0.f, ai = 0.f;
            #pragma unroll
            for (int j = 0; j < 4; j++) {
                // d = m0[i>>1][j>>1] * m1[i&1][j&1]
                float dr = m0r[i >> 1][j >> 1] * m1r[i & 1][j & 1]
                         - m0i[i >> 1][j >> 1] * m1i[i & 1][j & 1];
                float di = m0r[i >> 1][j >> 1] * m1i[i & 1][j & 1]
                         + m0i[i >> 1][j >> 1] * m1r[i & 1][j & 1];
                ar += dr * tr[j] - di * ti[j];
                ai += dr * ti[j] + di * tr[j];
            }
            nr[i] = ar; ni[i] = ai;
        }

        // ---- CP: element 3 *= e^{i(p12+p13)}
        {
            float sn, cs; __sincosf(p[12] + p[13], &sn, &cs);
            float r = nr[3] * cs - ni[3] * sn;
            float im = nr[3] * sn + ni[3] * cs;
            nr[3] = r; ni[3] = im;
        }

        #pragma unroll
        for (int i = 0; i < 4; i++) { ur[i] = nr[i]; ui[i] = ni[i]; }
    }

    // ---- fold state phase ph_col into this column: V[:,col] = ph_col * u
    // ph = (1, -i, -i, -1);  (-i)*(r+ii) = i + (-r)i ; (-1)*(r+ii) = -r - ii
    if (col == 1 || col == 2) {
        #pragma unroll
        for (int i = 0; i < 4; i++) { float r = ur[i]; ur[i] = ui[i]; ui[i] = -r; }
    } else if (col == 3) {
        #pragma unroll
        for (int i = 0; i < 4; i++) { ur[i] = -ur[i]; ui[i] = -ui[i]; }
    }

    // ---- gather V into every lane (only lane 0 uses it)
    float Vr[4][4], Vi[4][4];
    #pragma unroll
    for (int j = 0; j < 4; j++)
        #pragma unroll
        for (int i = 0; i < 4; i++) {
            Vr[i][j] = __shfl_sync(FULL, ur[i], j);
            Vi[i][j] = __shfl_sync(FULL, ui[i], j);
        }

    if (lane == 0) {
        // A[j][k] = sum_i z_i (Vr[i][j]Vr[i][k] + Vi[i][j]Vi[i][k]), z=(1,1,-1,-1)
        float A[4][4];
        #pragma unroll
        for (int j = 0; j < 4; j++)
            #pragma unroll
            for (int k = 0; k < 4; k++) {
                float acc = 0.f;
                #pragma unroll
                for (int i = 0; i < 4; i++) {
                    float z = (i < 2) ? 1.f : -1.f;
                    acc += z * (Vr[i][j] * Vr[i][k] + Vi[i][j] * Vi[i][k]);
                }
                A[j][k] = acc;
            }

        float cC   = A[0][0] + A[1][1] + A[2][2] + A[3][3];
        float cC0  = A[0][0] + A[1][1] - A[2][2] - A[3][3];
        float cC1  = A[0][0] - A[1][1] + A[2][2] - A[3][3];
        float cCC  = A[0][0] - A[1][1] - A[2][2] + A[3][3];
        float cS1   = 2.f * (A[0][1] + A[2][3]);
        float cC0S1 = 2.f * (A[0][1] - A[2][3]);
        float cS0   = 2.f * (A[0][2] + A[1][3]);
        float cS0C1 = 2.f * (A[0][2] - A[1][3]);
        float cS0S1 = 2.f * (A[0][3] + A[1][2]);

        float w = 0.25f * W[0];
        g_k[0] = w * cC + bias[0];
        g_k[1] = w * cC0;
        g_k[2] = w * cC1;
        g_k[3] = w * cCC;
        g_k[4] = w * cS0;
        g_k[5] = w * cS1;
        g_k[6] = w * cS0C1;
        g_k[7] = w * cC0S1;
        g_k[8] = w * cS0S1;
    }
}

// ---------------------------------------------------------------------------
// Streaming kernel
// ---------------------------------------------------------------------------
__device__ __forceinline__ float eval_sample(float x0, float x1,
                                             const float k[9]) {
    float s0, c0, s1, c1;
    __sincosf(x0, &s0, &c0);
    __sincosf(x1, &s1, &c1);
    float v = k[0];
    v = fmaf(k[1], c0, v);
    v = fmaf(k[2], c1, v);
    v = fmaf(k[3], c0 * c1, v);
    v = fmaf(k[4], s0, v);
    v = fmaf(k[5], s1, v);
    v = fmaf(k[6], s0 * c1, v);
    v = fmaf(k[7], c0 * s1, v);
    v = fmaf(k[8], s0 * s1, v);
    return v;
}

// 8 samples / thread: four float4 loads (front-batched, MLP=4), two float4 stores.
__global__ void __launch_bounds__(256)
fraud_kernel8(const float4* __restrict__ x, float4* __restrict__ out, int nt) {
    int t = blockIdx.x * blockDim.x + threadIdx.x;
    float k[9];
    #pragma unroll
    for (int i = 0; i < 9; i++) k[i] = __ldg(&g_k[i]);
    if (t < nt) {
        float4 a = x[4 * t];
        float4 b = x[4 * t + 1];
        float4 c = x[4 * t + 2];
        float4 d = x[4 * t + 3];
        float4 r0, r1;
        r0.x = eval_sample(a.x, a.y, k);
        r0.y = eval_sample(a.z, a.w, k);
        r0.z = eval_sample(b.x, b.y, k);
        r0.w = eval_sample(b.z, b.w, k);
        r1.x = eval_sample(c.x, c.y, k);
        r1.y = eval_sample(c.z, c.w, k);
        r1.z = eval_sample(d.x, d.y, k);
        r1.w = eval_sample(d.z, d.w, k);
        out[2 * t] = r0;
        out[2 * t + 1] = r1;
    }
}

// Scalar fallback (not hit for this problem's shapes).
__global__ void __launch_bounds__(256)
fraud_kernel_scalar(const float2* __restrict__ x, float* __restrict__ out, int B) {
    int t = blockIdx.x * blockDim.x + threadIdx.x;
    float k[9];
    #pragma unroll
    for (int i = 0; i < 9; i++) k[i] = __ldg(&g_k[i]);
    if (t < B) {
        float2 a = x[t];
        out[t] = eval_sample(a.x, a.y, k);
    }
}

extern "C" void kernel_launch(void* const* d_in, const int* in_sizes, int n_in,
                              void* d_out, int out_size) {
    const float* x      = (const float*)d_in[0];
    const float* params = (const float*)d_in[1];
    const float* W      = (const float*)d_in[2];
    const float* bias   = (const float*)d_in[3];
    float* out = (float*)d_out;

    int L = in_sizes[1] / 14;
    setup_kernel<<<1, 32>>>(params, W, bias, L);

    int B = out_size;  // n_classes = 1 -> out_size == batch
    if ((B & 7) == 0) {
        int nt = B >> 3;
        int blocks = (nt + 255) / 256;
        fraud_kernel8<<<blocks, 256>>>((const float4*)x, (float4*)out, nt);
    } else {
        int blocks = (B + 255) / 256;
        fraud_kernel_scalar<<<blocks, 256>>>((const float2*)x, out, B);
    }
}